// round 5
// baseline (speedup 1.0000x reference)
#include <cuda_runtime.h>
#include <stdint.h>

// Bidirectional chamfer distance, B=4, N=M=5000, D=3.
// d2/2 = hq + hr - q.r. 8 queries/thread as 4 f32x2 packed pairs; refs
// broadcast from SMEM duplicated {x,x,y,y,z,z,h,h} -> ld.shared.v2.u64 gives
// aligned f32x2 operands. fma.rn.f32x2 + scalar FMNMX. S=29 ref-split sized
// for a SINGLE wave: grid 1160 <= 148 SM x 8 CTA (64 regs).

#define B_    4
#define N_    5000
#define S_    29         // ref split (split-K over refs)
#define CHUNK 173        // ceil(N_/S_); 29*173 = 5017 >= 5000
#define TPB   128        // threads per block
#define QPT   8          // queries per thread
#define QPB   1024       // queries per block
#define QB    5          // ceil(5000/1024)
#define RPAD  176        // padded refs per chunk (multiple of 4)
#define PSTR  32         // padded partial stride (floats), aligned float4 rows
#define NBLK_B 40
#define TPB_B  256

// Scratch: partial (unclamped) d2 per (dir,b,q,s), then block sums.
__device__ __align__(16) float g_part[2 * B_ * N_ * PSTR];   // 5.1 MB
__device__ float g_bsums[NBLK_B];

__global__ __launch_bounds__(TPB) void chamfer_main(const float* __restrict__ pred,
                                                    const float* __restrict__ gt) {
    __shared__ __align__(32) float smf[RPAD * 8];   // 5.5 KB

    const int qb  = blockIdx.x;          // query block 0..QB-1
    const int bd  = blockIdx.y;          // dir*B_ + b, 0..7
    const int s   = blockIdx.z;          // ref split 0..S_-1
    const int dir = bd >> 2;             // 0: pred->gt, 1: gt->pred
    const int b   = bd & 3;

    const float* __restrict__ qbase = (dir == 0 ? pred : gt) + b * N_ * 3;
    const float* __restrict__ rb    = (dir == 0 ? gt : pred) + b * N_ * 3;

    const int tid = threadIdx.x;
    const int r0g = s * CHUNK;           // first global ref index of this chunk

    // Cooperative load of the ref chunk, duplicated per point for f32x2 ops.
    for (int r = tid; r < RPAD; r += TPB) {
        const int g = r0g + r;
        float gx, gy, gz, h;
        if (r < CHUNK && g < N_) {
            gx = rb[g * 3 + 0];
            gy = rb[g * 3 + 1];
            gz = rb[g * 3 + 2];
            h  = 0.5f * (gx * gx + gy * gy + gz * gz);
        } else {
            gx = 0.0f; gy = 0.0f; gz = 0.0f; h = 1.0e30f;  // sentinel
        }
        smf[r * 8 + 0] = gx; smf[r * 8 + 1] = gx;
        smf[r * 8 + 2] = gy; smf[r * 8 + 3] = gy;
        smf[r * 8 + 4] = gz; smf[r * 8 + 5] = gz;
        smf[r * 8 + 6] = h;  smf[r * 8 + 7] = h;
    }

    // 8 queries per thread: q_k = qb*QPB + tid + k*TPB, packed pairs (2j, 2j+1).
    int   qi[QPT];
    float hq[QPT];
    uint64_t nx2[4], ny2[4], nz2[4];
#pragma unroll
    for (int j = 0; j < 4; ++j) {
        int k0 = 2 * j, k1 = 2 * j + 1;
        int a = qb * QPB + tid + k0 * TPB;
        int c = qb * QPB + tid + k1 * TPB;
        qi[k0] = a; qi[k1] = c;
        int ac = a < N_ ? a : N_ - 1;
        int cc = c < N_ ? c : N_ - 1;
        float ax = qbase[ac * 3 + 0], ay = qbase[ac * 3 + 1], az = qbase[ac * 3 + 2];
        float bx = qbase[cc * 3 + 0], by = qbase[cc * 3 + 1], bz = qbase[cc * 3 + 2];
        hq[k0] = 0.5f * (ax * ax + ay * ay + az * az);
        hq[k1] = 0.5f * (bx * bx + by * by + bz * bz);
        asm("mov.b64 %0, {%1, %2};" : "=l"(nx2[j]) : "f"(-ax), "f"(-bx));
        asm("mov.b64 %0, {%1, %2};" : "=l"(ny2[j]) : "f"(-ay), "f"(-by));
        asm("mov.b64 %0, {%1, %2};" : "=l"(nz2[j]) : "f"(-az), "f"(-bz));
    }

    __syncthreads();

    uint32_t sbase = (uint32_t)__cvta_generic_to_shared(smf);

    float mn[QPT];
#pragma unroll
    for (int k = 0; k < QPT; ++k) mn[k] = 1.0e30f;

#pragma unroll 4
    for (int p = 0; p < RPAD; ++p) {
        uint64_t rx, ry, rz, rh;
        uint32_t a = sbase + p * 32;
        asm("ld.shared.v2.u64 {%0, %1}, [%2];" : "=l"(rx), "=l"(ry) : "r"(a));
        asm("ld.shared.v2.u64 {%0, %1}, [%2];" : "=l"(rz), "=l"(rh) : "r"(a + 16));
#pragma unroll
        for (int j = 0; j < 4; ++j) {
            // u = h - q.r for the two packed queries; unpack mov elided by ptxas.
            float u0, u1;
            asm("{\n\t"
                ".reg .b64 t;\n\t"
                "fma.rn.f32x2 t, %2, %3, %4;\n\t"
                "fma.rn.f32x2 t, %5, %6, t;\n\t"
                "fma.rn.f32x2 t, %7, %8, t;\n\t"
                "mov.b64 {%0, %1}, t;\n\t"
                "}"
                : "=f"(u0), "=f"(u1)
                : "l"(nz2[j]), "l"(rz), "l"(rh),
                  "l"(ny2[j]), "l"(ry),
                  "l"(nx2[j]), "l"(rx));
            mn[2 * j]     = fminf(mn[2 * j], u0);
            mn[2 * j + 1] = fminf(mn[2 * j + 1], u1);
        }
    }

    // Write partial (unclamped) d2 for this ref chunk; min over s + clamp later.
    const int base = (dir * B_ + b) * N_;
#pragma unroll
    for (int k = 0; k < QPT; ++k) {
        if (qi[k] < N_) g_part[(base + qi[k]) * PSTR + s] = 2.0f * (hq[k] + mn[k]);
    }
}

__global__ __launch_bounds__(TPB_B) void chamfer_reduce1() {
    __shared__ float ssum[TPB_B];
    const int gtid = blockIdx.x * TPB_B + threadIdx.x;
    float acc = 0.0f;
    for (int q = gtid; q < 2 * B_ * N_; q += NBLK_B * TPB_B) {
        const float* row = g_part + q * PSTR;
        const float4* p4 = (const float4*)row;
        float m = 1.0e30f;
#pragma unroll
        for (int i = 0; i < 7; ++i) {   // entries 0..27
            float4 a = p4[i];
            m = fminf(m, fminf(fminf(a.x, a.y), fminf(a.z, a.w)));
        }
        m = fminf(m, row[28]);          // entry 28 (S_=29 total)
        acc += fmaxf(m, 0.0f);
    }
    ssum[threadIdx.x] = acc;
    __syncthreads();
    for (int off = TPB_B / 2; off > 0; off >>= 1) {
        if (threadIdx.x < off) ssum[threadIdx.x] += ssum[threadIdx.x + off];
        __syncthreads();
    }
    if (threadIdx.x == 0) g_bsums[blockIdx.x] = ssum[0];
}

__global__ void chamfer_reduce2(float* __restrict__ out) {
    __shared__ float sv[64];
    float v = (threadIdx.x < NBLK_B) ? g_bsums[threadIdx.x] : 0.0f;
    sv[threadIdx.x] = v;
    __syncthreads();
    if (threadIdx.x == 0) {
        float t = 0.0f;
#pragma unroll
        for (int i = 0; i < 64; ++i) t += sv[i];
        out[0] = t * (1.0f / (B_ * N_));
    }
}

extern "C" void kernel_launch(void* const* d_in, const int* in_sizes, int n_in,
                              void* d_out, int out_size) {
    const float* pred = (const float*)d_in[0];
    const float* gt   = (const float*)d_in[1];
    dim3 grid(QB, 2 * B_, S_);
    chamfer_main<<<grid, TPB>>>(pred, gt);
    chamfer_reduce1<<<NBLK_B, TPB_B>>>();
    chamfer_reduce2<<<1, 64>>>((float*)d_out);
}

// round 6
// speedup vs baseline: 1.0491x; 1.0491x over previous
#include <cuda_runtime.h>
#include <stdint.h>

// Bidirectional chamfer distance, B=4, N=M=5000, D=3.
// d2/2 = hq + hr - q.r. 8 queries/thread as 4 f32x2 packed pairs; refs
// broadcast from SMEM duplicated {x,x,y,y,z,z,h,h} -> ld.shared.v2.u64 gives
// aligned f32x2 operands. fma.rn.f32x2 + scalar FMNMX.
// launch_bounds(128,10) pins regs <= 51 -> 10 CTAs/SM; S=37 makes the grid
// exactly one full wave: 5*8*37 = 1480 = 148 SMs x 10 CTAs.

#define B_    4
#define N_    5000
#define S_    37         // ref split (split-K over refs)
#define CHUNK 136        // ceil(N_/S_); 37*136 = 5032 >= 5000
#define TPB   128        // threads per block
#define QPT   8          // queries per thread
#define QPB   1024       // queries per block
#define QB    5          // ceil(5000/1024)
#define RPAD  136        // refs per chunk in smem (multiple of 8)
#define PSTR  40         // padded partial stride (floats)
#define NBLK_B 40
#define TPB_B  256

// Scratch: partial (unclamped) d2 per (dir,b,q,s), then block sums.
__device__ __align__(16) float g_part[2 * B_ * N_ * PSTR];   // 6.4 MB
__device__ float g_bsums[NBLK_B];

__global__ __launch_bounds__(TPB, 10) void chamfer_main(const float* __restrict__ pred,
                                                        const float* __restrict__ gt) {
    __shared__ __align__(32) float smf[RPAD * 8];   // 4.25 KB

    const int qb  = blockIdx.x;          // query block 0..QB-1
    const int bd  = blockIdx.y;          // dir*B_ + b, 0..7
    const int s   = blockIdx.z;          // ref split 0..S_-1
    const int dir = bd >> 2;             // 0: pred->gt, 1: gt->pred
    const int b   = bd & 3;

    const float* __restrict__ qbase = (dir == 0 ? pred : gt) + b * N_ * 3;
    const float* __restrict__ rb    = (dir == 0 ? gt : pred) + b * N_ * 3;

    const int tid = threadIdx.x;
    const int r0g = s * CHUNK;           // first global ref index of this chunk

    // Cooperative load of the ref chunk, duplicated per point for f32x2 ops.
    for (int r = tid; r < RPAD; r += TPB) {
        const int g = r0g + r;
        float gx, gy, gz, h;
        if (g < N_) {
            gx = rb[g * 3 + 0];
            gy = rb[g * 3 + 1];
            gz = rb[g * 3 + 2];
            h  = 0.5f * (gx * gx + gy * gy + gz * gz);
        } else {
            gx = 0.0f; gy = 0.0f; gz = 0.0f; h = 1.0e30f;  // sentinel
        }
        smf[r * 8 + 0] = gx; smf[r * 8 + 1] = gx;
        smf[r * 8 + 2] = gy; smf[r * 8 + 3] = gy;
        smf[r * 8 + 4] = gz; smf[r * 8 + 5] = gz;
        smf[r * 8 + 6] = h;  smf[r * 8 + 7] = h;
    }

    // 8 queries per thread: q_k = qb*QPB + tid + k*TPB, packed pairs (2j, 2j+1).
    int   qi[QPT];
    float hq[QPT];
    uint64_t nx2[4], ny2[4], nz2[4];
#pragma unroll
    for (int j = 0; j < 4; ++j) {
        int k0 = 2 * j, k1 = 2 * j + 1;
        int a = qb * QPB + tid + k0 * TPB;
        int c = qb * QPB + tid + k1 * TPB;
        qi[k0] = a; qi[k1] = c;
        int ac = a < N_ ? a : N_ - 1;
        int cc = c < N_ ? c : N_ - 1;
        float ax = qbase[ac * 3 + 0], ay = qbase[ac * 3 + 1], az = qbase[ac * 3 + 2];
        float bx = qbase[cc * 3 + 0], by = qbase[cc * 3 + 1], bz = qbase[cc * 3 + 2];
        hq[k0] = 0.5f * (ax * ax + ay * ay + az * az);
        hq[k1] = 0.5f * (bx * bx + by * by + bz * bz);
        asm("mov.b64 %0, {%1, %2};" : "=l"(nx2[j]) : "f"(-ax), "f"(-bx));
        asm("mov.b64 %0, {%1, %2};" : "=l"(ny2[j]) : "f"(-ay), "f"(-by));
        asm("mov.b64 %0, {%1, %2};" : "=l"(nz2[j]) : "f"(-az), "f"(-bz));
    }

    __syncthreads();

    uint32_t sbase = (uint32_t)__cvta_generic_to_shared(smf);

    float mn[QPT];
#pragma unroll
    for (int k = 0; k < QPT; ++k) mn[k] = 1.0e30f;

#pragma unroll 8
    for (int p = 0; p < RPAD; ++p) {
        uint64_t rx, ry, rz, rh;
        uint32_t a = sbase + p * 32;
        asm("ld.shared.v2.u64 {%0, %1}, [%2];" : "=l"(rx), "=l"(ry) : "r"(a));
        asm("ld.shared.v2.u64 {%0, %1}, [%2];" : "=l"(rz), "=l"(rh) : "r"(a + 16));
#pragma unroll
        for (int j = 0; j < 4; ++j) {
            // u = h - q.r for the two packed queries; unpack mov elided by ptxas.
            float u0, u1;
            asm("{\n\t"
                ".reg .b64 t;\n\t"
                "fma.rn.f32x2 t, %2, %3, %4;\n\t"
                "fma.rn.f32x2 t, %5, %6, t;\n\t"
                "fma.rn.f32x2 t, %7, %8, t;\n\t"
                "mov.b64 {%0, %1}, t;\n\t"
                "}"
                : "=f"(u0), "=f"(u1)
                : "l"(nz2[j]), "l"(rz), "l"(rh),
                  "l"(ny2[j]), "l"(ry),
                  "l"(nx2[j]), "l"(rx));
            mn[2 * j]     = fminf(mn[2 * j], u0);
            mn[2 * j + 1] = fminf(mn[2 * j + 1], u1);
        }
    }

    // Write partial (unclamped) d2 for this ref chunk; min over s + clamp later.
    const int base = (dir * B_ + b) * N_;
#pragma unroll
    for (int k = 0; k < QPT; ++k) {
        if (qi[k] < N_) g_part[(base + qi[k]) * PSTR + s] = 2.0f * (hq[k] + mn[k]);
    }
}

__global__ __launch_bounds__(TPB_B) void chamfer_reduce1() {
    __shared__ float ssum[TPB_B];
    const int gtid = blockIdx.x * TPB_B + threadIdx.x;
    float acc = 0.0f;
    for (int q = gtid; q < 2 * B_ * N_; q += NBLK_B * TPB_B) {
        const float* row = g_part + q * PSTR;
        const float4* p4 = (const float4*)row;
        float m = 1.0e30f;
#pragma unroll
        for (int i = 0; i < 9; ++i) {   // entries 0..35
            float4 a = p4[i];
            m = fminf(m, fminf(fminf(a.x, a.y), fminf(a.z, a.w)));
        }
        m = fminf(m, row[36]);          // entry 36 (S_=37 total)
        acc += fmaxf(m, 0.0f);
    }
    ssum[threadIdx.x] = acc;
    __syncthreads();
    for (int off = TPB_B / 2; off > 0; off >>= 1) {
        if (threadIdx.x < off) ssum[threadIdx.x] += ssum[threadIdx.x + off];
        __syncthreads();
    }
    if (threadIdx.x == 0) g_bsums[blockIdx.x] = ssum[0];
}

__global__ void chamfer_reduce2(float* __restrict__ out) {
    __shared__ float sv[64];
    float v = (threadIdx.x < NBLK_B) ? g_bsums[threadIdx.x] : 0.0f;
    sv[threadIdx.x] = v;
    __syncthreads();
    if (threadIdx.x == 0) {
        float t = 0.0f;
#pragma unroll
        for (int i = 0; i < 64; ++i) t += sv[i];
        out[0] = t * (1.0f / (B_ * N_));
    }
}

extern "C" void kernel_launch(void* const* d_in, const int* in_sizes, int n_in,
                              void* d_out, int out_size) {
    const float* pred = (const float*)d_in[0];
    const float* gt   = (const float*)d_in[1];
    dim3 grid(QB, 2 * B_, S_);
    chamfer_main<<<grid, TPB>>>(pred, gt);
    chamfer_reduce1<<<NBLK_B, TPB_B>>>();
    chamfer_reduce2<<<1, 64>>>((float*)d_out);
}